// round 9
// baseline (speedup 1.0000x reference)
#include <cuda_runtime.h>
#include <cuda_bf16.h>
#include <cstdint>

// ============================================================================
// Fused 2-layer SimpleRNN, round 7.
// vs R5: epilogue tanh computed in packed bf16 (tanh.approx.bf16x2) -> MUFU
// instruction count halved (64 -> 32 per step per thread); xproj rewritten
// with Wx1 staged in SMEM (16 vocab rows/block) cutting its L2 traffic 4x.
// ============================================================================

#define VOCAB   10000
#define B_TOT   16384
#define T_SEQ   80
#define E_DIM   100
#define U_DIM   64
#define M_TILE  128
#define NTHR    256

#define HSTRB   144     // W tile row stride bytes (72 bf16)
#define STGSTR  144     // staging row stride bytes
#define STG_PER_WARP (16 * STGSTR)   // 2304 B

// SMEM layout (bytes)
#define OFF_WH1  0                          // 64*144 = 9216 (persistent)
#define OFF_STG  (OFF_WH1 + 64*HSTRB)       // 8 warps * 2304 = 18432
#define SMEM_TOTAL (OFF_STG + 8*STG_PER_WARP + 64)

// Projected embedding table: E'[v][u] = emb[v]@Wx1[:,u] + b1[u]  (bf16)
__device__ __nv_bfloat16 g_Etab[VOCAB * U_DIM];

// ---------------------------------------------------------------------------
__device__ __forceinline__ uint32_t smem_u32(const void* p) {
    uint32_t a;
    asm("{ .reg .u64 t; cvta.to.shared.u64 t, %1; cvt.u32.u64 %0, t; }"
        : "=r"(a) : "l"(p));
    return a;
}
__device__ __forceinline__ uint32_t pack_bf16x2(float lo, float hi) {
    uint32_t r;
    asm("cvt.rn.bf16x2.f32 %0, %1, %2;" : "=r"(r) : "f"(hi), "f"(lo));
    return r;
}
// packed bf16x2 tanh: one MUFU op for two values, result already A-frag packed
__device__ __forceinline__ uint32_t tanh_b2(uint32_t p) {
    uint32_t r;
    asm("tanh.approx.bf16x2 %0, %1;" : "=r"(r) : "r"(p));
    return r;
}
__device__ __forceinline__ float bf16_lo(uint32_t p) { return __uint_as_float(p << 16); }
__device__ __forceinline__ float bf16_hi(uint32_t p) { return __uint_as_float(p & 0xffff0000u); }

__device__ __forceinline__ void ldsm4(uint32_t a[4], uint32_t addr) {
    asm volatile("ldmatrix.sync.aligned.m8n8.x4.shared.b16 {%0,%1,%2,%3}, [%4];"
                 : "=r"(a[0]), "=r"(a[1]), "=r"(a[2]), "=r"(a[3]) : "r"(addr));
}
__device__ __forceinline__ void mma16816(float c[4], const uint32_t a[4],
                                         uint32_t b0, uint32_t b1) {
    asm volatile("mma.sync.aligned.m16n8k16.row.col.f32.bf16.bf16.f32 "
                 "{%0,%1,%2,%3}, {%4,%5,%6,%7}, {%8,%9}, {%0,%1,%2,%3};"
                 : "+f"(c[0]), "+f"(c[1]), "+f"(c[2]), "+f"(c[3])
                 : "r"(a[0]), "r"(a[1]), "r"(a[2]), "r"(a[3]),
                   "r"(b0), "r"(b1));
}

// ---------------------------------------------------------------------------
// Kernel 1: E'[v] = emb[v] @ Wx1 + b1.  16 vocab rows per block; Wx1 staged
// in SMEM once per block (cuts Wx1 L2 refetch 4x vs 4-row blocks).
// ---------------------------------------------------------------------------
#define XP_ROWS 16
__global__ void __launch_bounds__(256)
xproj_kernel(const float* __restrict__ emb,
             const float* __restrict__ Wx1,
             const float* __restrict__ b1)
{
    __shared__ float wxs[E_DIM * U_DIM];     // [k][u], 25.6 KB
    __shared__ float er[XP_ROWS][E_DIM];     // 6.4 KB
    const int tid = threadIdx.x;
    const int v0  = blockIdx.x * XP_ROWS;

    for (int i = tid; i < E_DIM * U_DIM; i += 256) wxs[i] = __ldg(Wx1 + i);
    for (int i = tid; i < XP_ROWS * E_DIM; i += 256) {
        int v = i / E_DIM, k = i - v * E_DIM;
        er[v][k] = (v0 + v < VOCAB) ? emb[(size_t)(v0 + v) * E_DIM + k] : 0.0f;
    }
    __syncthreads();

    const int u  = tid & 63;
    const int ry = tid >> 6;                 // 0..3
    const float bias = __ldg(b1 + u);
#pragma unroll
    for (int rr = 0; rr < 4; rr++) {
        const int r = ry * 4 + rr;
        const int v = v0 + r;
        if (v >= VOCAB) break;
        float s = bias;
        const float4* er4 = (const float4*)er[r];
#pragma unroll 5
        for (int kc = 0; kc < E_DIM / 4; kc++) {
            float4 e = er4[kc];
            s = fmaf(e.x, wxs[(4 * kc + 0) * U_DIM + u], s);
            s = fmaf(e.y, wxs[(4 * kc + 1) * U_DIM + u], s);
            s = fmaf(e.z, wxs[(4 * kc + 2) * U_DIM + u], s);
            s = fmaf(e.w, wxs[(4 * kc + 3) * U_DIM + u], s);
        }
        g_Etab[v * U_DIM + u] = __float2bfloat16(s);
    }
}

// ---------------------------------------------------------------------------
// Kernel 2: recurrent loop. Warp owns 16 rows; h1/h2 live in registers.
// ---------------------------------------------------------------------------
__global__ void __launch_bounds__(NTHR, 1)
rnn_loop_kernel(const int* __restrict__ tokens,
                const float* __restrict__ Wh1,
                const float* __restrict__ Wx2, const float* __restrict__ Wh2,
                const float* __restrict__ b2,
                const float* __restrict__ Wd, const float* __restrict__ bd,
                float* __restrict__ out)
{
    extern __shared__ unsigned char sm[];
    const uint32_t smb = smem_u32(sm);

    const int tid  = threadIdx.x;
    const int wid  = tid >> 5;
    const int lane = tid & 31;
    const int growbase = blockIdx.x * M_TILE + wid * 16;

    // ---- build W^T tiles [n][k], stride 72 bf16 --------------------------
    {
        __nv_bfloat16* wh1 = (__nv_bfloat16*)(sm + OFF_WH1);
        __nv_bfloat16* wx2 = (__nv_bfloat16*)(sm + OFF_STG);          // transient
        __nv_bfloat16* wh2 = (__nv_bfloat16*)(sm + OFF_STG + 9216);   // transient
        for (int i = tid; i < U_DIM * 72; i += NTHR) {
            int n = i / 72, k = i - n * 72;
            bool ok = (k < U_DIM);
            wh1[i] = ok ? __float2bfloat16(Wh1[k * U_DIM + n]) : __float2bfloat16(0.0f);
            wx2[i] = ok ? __float2bfloat16(Wx2[k * U_DIM + n]) : __float2bfloat16(0.0f);
            wh2[i] = ok ? __float2bfloat16(Wh2[k * U_DIM + n]) : __float2bfloat16(0.0f);
        }
    }
    __syncthreads();

    // ---- ldmatrix lane addressing ----------------------------------------
    const uint32_t aRow = (uint32_t)(lane & 15);
    const uint32_t aK16 = (uint32_t)(lane >> 4) * 16;
    const uint32_t bRow = (uint32_t)((lane & 7) + ((lane >> 4) << 3));
    const uint32_t bK16 = (uint32_t)((lane >> 3) & 1) * 16;

    const uint32_t wh1B_lane = smb + OFF_WH1 + bRow * HSTRB + bK16;
    const uint32_t wx2B_lane = smb + OFF_STG + bRow * HSTRB + bK16;
    const uint32_t wh2B_lane = smb + OFF_STG + 9216 + bRow * HSTRB + bK16;

    const int cr = lane >> 2;          // c/a-frag row within m16
    const int cq = (lane & 3) * 2;     // c/a-frag col-pair base within 8

    // ---- hoist layer-2 weights into registers (128 regs) ------------------
    uint32_t wx2r[4][4][4], wh2r[4][4][4];
#pragma unroll
    for (int kt = 0; kt < 4; kt++)
#pragma unroll
        for (int np = 0; np < 4; np++) {
            ldsm4(wx2r[kt][np], wx2B_lane + np * 16 * HSTRB + kt * 32);
            ldsm4(wh2r[kt][np], wh2B_lane + np * 16 * HSTRB + kt * 32);
        }
    __syncthreads();   // weights now in regs; staging area becomes free

    // ---- warp-private E' staging -----------------------------------------
    const uint32_t stgA_lane = smb + OFF_STG + wid * STG_PER_WARP
                             + aRow * STGSTR + aK16;                 // ldsm read
    const int ldg_row   = lane >> 3;        // 0..3 within 4-row group
    const int ldg_chunk = lane & 7;         // 16B chunk within 128B row
    unsigned char* stg_ptr = sm + OFF_STG + wid * STG_PER_WARP + ldg_chunk * 16;

    // ---- per-lane b2 (layer-2 acc init) ----------------------------------
    float b2x[8], b2y[8];
#pragma unroll
    for (int nt = 0; nt < 8; nt++) {
        b2x[nt] = __ldg(b2 + nt * 8 + cq);
        b2y[nt] = __ldg(b2 + nt * 8 + cq + 1);
    }

    // ---- register-resident state fragments -------------------------------
    uint32_t h1f[4][4], h2f[4][4];
#pragma unroll
    for (int kt = 0; kt < 4; kt++)
#pragma unroll
        for (int j = 0; j < 4; j++) { h1f[kt][j] = 0u; h2f[kt][j] = 0u; }

    // ---- prefetch machinery ----------------------------------------------
    const uint4* Et4 = (const uint4*)g_Etab;   // 8 x uint4 per row
    uint4 pv[4];
    int tokreg = 0;

    auto prefetch_load = [&](int t) {
        int r = 0;
        if (lane < 16) r = __ldg(tokens + (size_t)(growbase + lane) * T_SEQ + t);
        tokreg = r;
#pragma unroll
        for (int i = 0; i < 4; i++) {
            int row = 4 * i + ldg_row;
            int tok = __shfl_sync(0xffffffffu, tokreg, row);
            pv[i] = __ldg(Et4 + (size_t)tok * 8 + ldg_chunk);
        }
    };
    auto prefetch_store = [&]() {
#pragma unroll
        for (int i = 0; i < 4; i++) {
            int row = 4 * i + ldg_row;
            *(uint4*)(stg_ptr + row * STGSTR) = pv[i];
        }
    };

    prefetch_load(0);
    prefetch_store();
    __syncwarp();

    // ---- T loop (state in regs; staging is the only steady SMEM traffic) --
    for (int t = 0; t < T_SEQ; ++t) {
        // acc init = xp from staged E' (ldsm4 per 16-col chunk -> C layout)
        float acc[8][4];
#pragma unroll
        for (int kc = 0; kc < 4; kc++) {
            uint32_t e[4]; ldsm4(e, stgA_lane + kc * 32);
            acc[2 * kc][0]     = bf16_lo(e[0]); acc[2 * kc][1]     = bf16_hi(e[0]);
            acc[2 * kc][2]     = bf16_lo(e[1]); acc[2 * kc][3]     = bf16_hi(e[1]);
            acc[2 * kc + 1][0] = bf16_lo(e[2]); acc[2 * kc + 1][1] = bf16_hi(e[2]);
            acc[2 * kc + 1][2] = bf16_lo(e[3]); acc[2 * kc + 1][3] = bf16_hi(e[3]);
        }
        __syncwarp();                       // all lanes done reading staging
        if (t + 1 < T_SEQ) prefetch_load(t + 1);   // LDGs overlap MMAs

        // ---- layer 1: acc += h1 @ Wh1 (B from SMEM) ----
#pragma unroll
        for (int kt = 0; kt < 4; kt++) {
#pragma unroll
            for (int np = 0; np < 4; np++) {
                uint32_t b[4]; ldsm4(b, wh1B_lane + np * 16 * HSTRB + kt * 32);
                mma16816(acc[2 * np],     h1f[kt], b[0], b[1]);
                mma16816(acc[2 * np + 1], h1f[kt], b[2], b[3]);
            }
        }

        // ---- epilogue 1: h1 = tanh_bf16x2(pack(acc)) -> A-fragments ----
        // a-frag: [0]=row cr k-lo, [1]=row cr+8 k-lo, [2]=row cr k-hi, [3]=row cr+8 k-hi
#pragma unroll
        for (int kt = 0; kt < 4; kt++) {
            h1f[kt][0] = tanh_b2(pack_bf16x2(acc[2 * kt][0],     acc[2 * kt][1]));
            h1f[kt][1] = tanh_b2(pack_bf16x2(acc[2 * kt][2],     acc[2 * kt][3]));
            h1f[kt][2] = tanh_b2(pack_bf16x2(acc[2 * kt + 1][0], acc[2 * kt + 1][1]));
            h1f[kt][3] = tanh_b2(pack_bf16x2(acc[2 * kt + 1][2], acc[2 * kt + 1][3]));
        }

        if (t + 1 < T_SEQ) prefetch_store();   // STS mid-step (LDG data ready)

        // ---- layer 2: acc = b2 + h1 @ Wx2 + h2 @ Wh2 (B in regs) ----
#pragma unroll
        for (int nt = 0; nt < 8; nt++) {
            acc[nt][0] = b2x[nt]; acc[nt][1] = b2y[nt];
            acc[nt][2] = b2x[nt]; acc[nt][3] = b2y[nt];
        }
#pragma unroll
        for (int kt = 0; kt < 4; kt++) {
#pragma unroll
            for (int np = 0; np < 4; np++) {
                mma16816(acc[2 * np],     h1f[kt], wx2r[kt][np][0], wx2r[kt][np][1]);
                mma16816(acc[2 * np + 1], h1f[kt], wx2r[kt][np][2], wx2r[kt][np][3]);
            }
        }
#pragma unroll
        for (int kt = 0; kt < 4; kt++) {
#pragma unroll
            for (int np = 0; np < 4; np++) {
                mma16816(acc[2 * np],     h2f[kt], wh2r[kt][np][0], wh2r[kt][np][1]);
                mma16816(acc[2 * np + 1], h2f[kt], wh2r[kt][np][2], wh2r[kt][np][3]);
            }
        }

        // ---- epilogue 2: h2 = tanh_bf16x2(pack(acc)) -> A-fragments ----
#pragma unroll
        for (int kt = 0; kt < 4; kt++) {
            h2f[kt][0] = tanh_b2(pack_bf16x2(acc[2 * kt][0],     acc[2 * kt][1]));
            h2f[kt][1] = tanh_b2(pack_bf16x2(acc[2 * kt][2],     acc[2 * kt][3]));
            h2f[kt][2] = tanh_b2(pack_bf16x2(acc[2 * kt + 1][0], acc[2 * kt + 1][1]));
            h2f[kt][3] = tanh_b2(pack_bf16x2(acc[2 * kt + 1][2], acc[2 * kt + 1][3]));
        }
        __syncwarp();    // staging stores visible for next iteration's ldsm
    }

    // ---- final dense + sigmoid from h2 register fragments ----------------
    // row cr: fragments [0] (cols 16kt+cq) and [2] (cols 16kt+8+cq)
    // row cr+8: fragments [1] and [3]
    {
        float la = 0.0f, lb = 0.0f;
#pragma unroll
        for (int kt = 0; kt < 4; kt++) {
            int c0 = 16 * kt + cq;
            float w0 = __ldg(Wd + c0),     w1 = __ldg(Wd + c0 + 1);
            float w8 = __ldg(Wd + c0 + 8), w9 = __ldg(Wd + c0 + 9);
            la = fmaf(bf16_lo(h2f[kt][0]), w0, la);
            la = fmaf(bf16_hi(h2f[kt][0]), w1, la);
            la = fmaf(bf16_lo(h2f[kt][2]), w8, la);
            la = fmaf(bf16_hi(h2f[kt][2]), w9, la);
            lb = fmaf(bf16_lo(h2f[kt][1]), w0, lb);
            lb = fmaf(bf16_hi(h2f[kt][1]), w1, lb);
            lb = fmaf(bf16_lo(h2f[kt][3]), w8, lb);
            lb = fmaf(bf16_hi(h2f[kt][3]), w9, lb);
        }
        la += __shfl_xor_sync(0xffffffffu, la, 1);
        la += __shfl_xor_sync(0xffffffffu, la, 2);
        lb += __shfl_xor_sync(0xffffffffu, lb, 1);
        lb += __shfl_xor_sync(0xffffffffu, lb, 2);
        if ((lane & 3) == 0) {
            float bdv = __ldg(bd);
            out[growbase + cr]     = 1.0f / (1.0f + __expf(-(la + bdv)));
            out[growbase + cr + 8] = 1.0f / (1.0f + __expf(-(lb + bdv)));
        }
    }
}

// ---------------------------------------------------------------------------
extern "C" void kernel_launch(void* const* d_in, const int* in_sizes, int n_in,
                              void* d_out, int out_size) {
    (void)in_sizes; (void)n_in; (void)out_size;
    cudaFuncSetAttribute(rnn_loop_kernel,
                         cudaFuncAttributeMaxDynamicSharedMemorySize, SMEM_TOTAL);

    xproj_kernel<<<(VOCAB + XP_ROWS - 1) / XP_ROWS, 256>>>(
        (const float*)d_in[1],   // emb
        (const float*)d_in[2],   // Wx1
        (const float*)d_in[4]);  // b1

    rnn_loop_kernel<<<B_TOT / M_TILE, NTHR, SMEM_TOTAL>>>(
        (const int*)d_in[0],     // tokens
        (const float*)d_in[3],   // Wh1
        (const float*)d_in[5],   // Wx2
        (const float*)d_in[6],   // Wh2
        (const float*)d_in[7],   // b2
        (const float*)d_in[8],   // Wd
        (const float*)d_in[9],   // bd
        (float*)d_out);
}